// round 14
// baseline (speedup 1.0000x reference)
#include <cuda_runtime.h>
#include <mma.h>
#include <math.h>

using namespace nvcuda;

// Problem constants
#define E_    4
#define D_    256
#define B_    16
#define T_    1024
#define NROW  (B_ * T_)          // 16384 rows (b*T + t)
#define LN_EPS 1e-5f

#define SEG_  8                  // scan segments
#define SEGL  (T_ / SEG_)        // 128 steps per segment (2^7)

#define ND_I  (NROW * D_)        // 4,194,304 elements per (k,e) activation tensor
static const size_t NDs = (size_t)NROW * D_;

// GEMM tile config
#define BM_ 128
#define BN_ 128
#define BK_ 16
#define ALD_ 20     // A smem leading dim (floats); stride 80B, conflict-free, mult of 4
#define BLD_ 136    // B smem leading dim; stride 544B
#define CLD_ 20     // epilogue staging leading dim

// dynamic smem layout (floats):
//   As: [2 buf][2 split][BM][ALD]   = 10240 floats
//   Bs: [2 buf][2 split][BK][BLD]   =  8704 floats
#define AS_FLOATS (2 * 2 * BM_ * ALD_)
#define BS_FLOATS (2 * 2 * BK_ * BLD_)
#define SMEM_FLOATS (AS_FLOATS + BS_FLOATS)
#define SMEM_BYTES  (SMEM_FLOATS * 4)            // 75,776 B

// ---------------------------------------------------------------------------
// Scratch (device globals — no allocation allowed).
//   g_u[k][e][n][d], k=0: real input -> scan output (in place)
//                    k=1: imag input -> scan output (in place)
//                    k=2: o -> "out" (mid0-mid1+o, in place)
__device__ float g_u[3 * E_ * ND_I];          // 201 MB
__device__ float g_h1[E_ * ND_I];             // 67 MB
__device__ float g_h2[E_ * ND_I];             // 67 MB
__device__ float g_gamma[E_ * D_];            // 4 KB
__device__ float g_segr[E_ * B_ * SEG_ * D_]; // segment-end real (512 KB)
__device__ float g_segi[E_ * B_ * SEG_ * D_]; // segment-end imag

// ---------------------------------------------------------------------------
__global__ void precompute_gamma(const float* __restrict__ pl) {
    int i = blockIdx.x * blockDim.x + threadIdx.x;
    if (i < E_ * D_) {
        g_gamma[i] = expf(pl[2 * E_ * D_ + i]);   // params_log (3,E,D), gamma = k2
    }
}

__device__ __forceinline__ float gelu_exact(float x) {
    return 0.5f * x * (1.0f + erff(x * 0.70710678118654752440f));
}

__device__ __forceinline__ float to_tf32(float x) {
    unsigned u;
    asm("cvt.rna.tf32.f32 %0, %1;" : "=r"(u) : "f"(x));
    return __uint_as_float(u);
}

// ---------------------------------------------------------------------------
// 3xTF32 tensor-core GEMM, 128x128x16 tiles, DOUBLE-BUFFERED, fused epilogues.
//   All GEMMs: A (16384 x 256) row-major, W (256 x 256) row-major, C (16384 x 256)
// EPI = 0: in_proj  z = k*4+e (12)  C = (A@W + b) * (k<2 ? gamma[e] : 1) -> g_u[z]
// EPI = 1: mid      z = e (4)  DUAL-K: acc = outR@W0 - outI@W1
//                   C = acc + b0 - b1 + o   -> g_u[8+e] (in place over o)
// EPI = 2: ffn1     z = e      C = gelu(out@W1 + b1) -> g_h1[e]
// EPI = 3: ffn2     z = e      C = h1@W2 + b2 + out  -> g_h2[e]
template <int EPI>
__global__ __launch_bounds__(256, 2) void tgemm_k(
    const float* __restrict__ P0,
    const float* __restrict__ P1,
    const float* __restrict__ P2)
{
    constexpr int BM = BM_, BN = BN_, BK = BK_;
    constexpr bool DUAL = (EPI == 1);
    constexpr int ALD = ALD_, BLD = BLD_, CLD = CLD_;

    extern __shared__ float smem[];
    // As[buf][hl][m][k], Bs[buf][hl][k][n]
    typedef float AsT[2][BM][ALD];
    typedef float BsT[2][BK][BLD];
    AsT* As = (AsT*)smem;                       // 2 bufs
    BsT* Bs = (BsT*)(smem + AS_FLOATS);         // 2 bufs
    // epilogue staging aliases the As region (dead after mainloop's final barrier)
    typedef float CstT[16][CLD];
    CstT* Cst = (CstT*)smem;                    // 8 warps x 16 x CLD

    const int tid = threadIdx.x;
    const int z = blockIdx.z;
    const int rowBase = blockIdx.x * BM;
    const int colBase = blockIdx.y * BN;

    const float *Aptr0, *Bptr0;
    const float *Aptr1 = nullptr, *Bptr1 = nullptr;

    if constexpr (EPI == 0) {
        Aptr0 = P0;                               // x
        Bptr0 = P1 + (size_t)z * 65536;           // in_proj_w[k][e]
    } else if constexpr (EPI == 1) {
        Aptr0 = g_u + (size_t)z * NDs;            // scan real output
        Bptr0 = P0 + (size_t)z * 65536;           // mid_w[0][e]
        Aptr1 = g_u + (size_t)(4 + z) * NDs;      // scan imag output
        Bptr1 = P0 + (size_t)(4 + z) * 65536;     // mid_w[1][e] (negated)
    } else if constexpr (EPI == 2) {
        Aptr0 = g_u + (size_t)(8 + z) * NDs;      // out
        Bptr0 = P0 + (size_t)z * 65536;           // ff_w1[e]
    } else {
        Aptr0 = g_h1 + (size_t)z * NDs;           // h1
        Bptr0 = P0 + (size_t)z * 65536;           // ff_w2[e]
    }

    // global-load assignments (2 float4 for A, 2 float4 for B per thread)
    const int arow = tid >> 2;            // 0..63 (and +64)
    const int akv  = (tid & 3) << 2;      // k sub-offset {0,4,8,12}
    const int brow = tid >> 5;            // 0..7 (and +8)
    const int bcol = (tid & 31) << 2;     // 0..124

    const int nsteps = DUAL ? 32 : 16;

    float4 ra0, ra1, rb0, rb1;

    auto ldg_step = [&](int step) {
        const float* Ag; const float* Bg; int k0; bool neg = false;
        if (!DUAL || step < 16) { Ag = Aptr0; Bg = Bptr0; k0 = step * BK; }
        else { Ag = Aptr1; Bg = Bptr1; k0 = (step - 16) * BK; neg = true; }
        ra0 = *(const float4*)&Ag[(size_t)(rowBase + arow)      * 256 + k0 + akv];
        ra1 = *(const float4*)&Ag[(size_t)(rowBase + arow + 64) * 256 + k0 + akv];
        rb0 = *(const float4*)&Bg[(size_t)(k0 + brow)     * 256 + colBase + bcol];
        rb1 = *(const float4*)&Bg[(size_t)(k0 + brow + 8) * 256 + colBase + bcol];
        if (DUAL && neg) {
            rb0.x = -rb0.x; rb0.y = -rb0.y; rb0.z = -rb0.z; rb0.w = -rb0.w;
            rb1.x = -rb1.x; rb1.y = -rb1.y; rb1.z = -rb1.z; rb1.w = -rb1.w;
        }
    };

    auto sts_step = [&](int buf) {
        float* A0 = &As[buf][0][0][0];
        float* A1 = &As[buf][1][0][0];
        float* B0 = &Bs[buf][0][0][0];
        float* B1 = &Bs[buf][1][0][0];
#pragma unroll
        for (int c = 0; c < 4; c++) {
            const float v0 = (&ra0.x)[c];
            const float v1 = (&ra1.x)[c];
            const float h0 = to_tf32(v0);
            const float h1 = to_tf32(v1);
            A0[(arow)      * ALD + akv + c] = h0;
            A1[(arow)      * ALD + akv + c] = to_tf32(v0 - h0);
            A0[(arow + 64) * ALD + akv + c] = h1;
            A1[(arow + 64) * ALD + akv + c] = to_tf32(v1 - h1);
            const float w0 = (&rb0.x)[c];
            const float w1 = (&rb1.x)[c];
            const float g0 = to_tf32(w0);
            const float g1 = to_tf32(w1);
            B0[(brow)     * BLD + bcol + c] = g0;
            B1[(brow)     * BLD + bcol + c] = to_tf32(w0 - g0);
            B0[(brow + 8) * BLD + bcol + c] = g1;
            B1[(brow + 8) * BLD + bcol + c] = to_tf32(w1 - g1);
        }
    };

    // warp tiling: 8 warps, warp tile 32x64 -> 2x4 wmma tiles of 16x16
    const int w    = tid >> 5;
    const int lane = tid & 31;
    const int wm   = w >> 1;     // 0..3, rows [wm*32, +32)
    const int wn   = w & 1;      // 0..1, cols [wn*64, +64)

    wmma::fragment<wmma::accumulator, 16, 16, 8, float> acc[2][4];
#pragma unroll
    for (int mi = 0; mi < 2; mi++)
#pragma unroll
        for (int ni = 0; ni < 4; ni++) wmma::fill_fragment(acc[mi][ni], 0.0f);

    // prologue: fill buffer 0
    ldg_step(0);
    sts_step(0);
    __syncthreads();

    int buf = 0;
#pragma unroll 1
    for (int step = 0; step < nsteps; ++step) {
        const bool has_next = (step + 1 < nsteps);
        if (has_next) ldg_step(step + 1);   // LDG latency hides under MMA phase

#pragma unroll
        for (int kk = 0; kk < BK; kk += 8) {
            wmma::fragment<wmma::matrix_a, 16, 16, 8, wmma::precision::tf32,
                           wmma::row_major> ah[2], al[2];
#pragma unroll
            for (int mi = 0; mi < 2; mi++) {
                wmma::load_matrix_sync(ah[mi], &As[buf][0][wm * 32 + mi * 16][kk], ALD);
                wmma::load_matrix_sync(al[mi], &As[buf][1][wm * 32 + mi * 16][kk], ALD);
            }
#pragma unroll
            for (int ni = 0; ni < 4; ni++) {
                wmma::fragment<wmma::matrix_b, 16, 16, 8, wmma::precision::tf32,
                               wmma::row_major> bh, bl;
                wmma::load_matrix_sync(bh, &Bs[buf][0][kk][wn * 64 + ni * 16], BLD);
                wmma::load_matrix_sync(bl, &Bs[buf][1][kk][wn * 64 + ni * 16], BLD);
#pragma unroll
                for (int mi = 0; mi < 2; mi++) {
                    wmma::mma_sync(acc[mi][ni], ah[mi], bh, acc[mi][ni]);  // hi*hi
                    wmma::mma_sync(acc[mi][ni], ah[mi], bl, acc[mi][ni]);  // hi*lo
                    wmma::mma_sync(acc[mi][ni], al[mi], bh, acc[mi][ni]);  // lo*hi
                }
            }
        }

        if (has_next) sts_step(buf ^ 1);    // fill idle buffer (consumed last iter)
        __syncthreads();                     // one barrier per iteration
        buf ^= 1;
    }

    // ---------------- epilogue (per-warp smem staging, aliases As) ----------
#pragma unroll
    for (int mi = 0; mi < 2; mi++) {
#pragma unroll
        for (int ni = 0; ni < 4; ni++) {
            wmma::store_matrix_sync(&Cst[w][0][0], acc[mi][ni], CLD, wmma::mem_row_major);
            __syncwarp();
#pragma unroll
            for (int q = lane; q < 256; q += 32) {
                const int r = q >> 4, c = q & 15;
                float v = Cst[w][r][c];
                const int n   = rowBase + wm * 32 + mi * 16 + r;
                const int col = colBase + wn * 64 + ni * 16 + c;
                const size_t idx = (size_t)n * 256 + col;

                if constexpr (EPI == 0) {
                    const int e = z & 3, k = z >> 2;
                    v += P2[(size_t)z * 256 + col];
                    if (k < 2) v *= g_gamma[e * 256 + col];
                    g_u[(size_t)z * NDs + idx] = v;
                } else if constexpr (EPI == 1) {
                    float* res = g_u + (size_t)(8 + z) * NDs;
                    v += P1[(size_t)z * 256 + col] - P1[(size_t)(4 + z) * 256 + col]
                         + res[idx];
                    res[idx] = v;   // "out" overwrites o in place
                } else if constexpr (EPI == 2) {
                    v = gelu_exact(v + P1[(size_t)z * 256 + col]);
                    g_h1[(size_t)z * NDs + idx] = v;
                } else {
                    const float* res = g_u + (size_t)(8 + z) * NDs;
                    v += P1[(size_t)z * 256 + col] + res[idx];
                    g_h2[(size_t)z * NDs + idx] = v;
                }
            }
            __syncwarp();
        }
    }
}

// ---------------------------------------------------------------------------
// Segmented LRU scan. f per (e,d): f = exp(-nu) * e^{i*theta}.
// Pass 1: per (e,b,s,d) thread, compute zero-init local end state of segment s.
// (Only s < SEG_-1 are needed: segment 7's end state is never a prefix.)
__global__ void scan_pass1(const float* __restrict__ pl) {
    const int idx = blockIdx.x * blockDim.x + threadIdx.x;  // (e,b,s,d)
    const int d = idx & 255;
    const int s = (idx >> 8) & (SEG_ - 1);
    const int b = (idx >> 11) & 15;
    const int e = idx >> 15;

    if (s == SEG_ - 1) return;   // last segment's end state is unused

    const float nu = expf(pl[0 * 1024 + e * 256 + d]);
    const float th = expf(pl[1 * 1024 + e * 256 + d]);
    const float mag = expf(-nu);
    float sn, cs;
    sincosf(th, &sn, &cs);       // th <= 2*pi: safe under fast math too
    const float fr = mag * cs;
    const float fi = mag * sn;

    const float* pr = g_u + (size_t)e * NDs + ((size_t)b * T_ + s * SEGL) * D_ + d;
    const float* pi = pr + (size_t)4 * NDs;

    float hr = 0.f, hi = 0.f;
#pragma unroll 1
    for (int t = 0; t < SEGL; t += 8) {
        float ur[8], ui[8];
#pragma unroll
        for (int j = 0; j < 8; j++) {
            ur[j] = pr[(size_t)j * D_];
            ui[j] = pi[(size_t)j * D_];
        }
#pragma unroll
        for (int j = 0; j < 8; j++) {
            const float nr = fr * hr - fi * hi + ur[j];
            const float ni = fr * hi + fi * hr + ui[j];
            hr = nr; hi = ni;
        }
        pr += 8 * D_;
        pi += 8 * D_;
    }

    // seg-end layout: [e][b][s][d]
    const size_t si = (((size_t)e * B_ + b) * SEG_ + s) * D_ + d;
    g_segr[si] = hr;
    g_segi[si] = hi;
}

// Pass 2: compute incoming prefix via f^SEGL (binary powering — avoids
// large-argument trig, which is inaccurate under fast math), then re-run
// the recurrence writing outputs in place; last segment writes hidden.
__global__ void scan_pass2(const float* __restrict__ pl, float* __restrict__ outp) {
    const int idx = blockIdx.x * blockDim.x + threadIdx.x;  // (e,b,s,d)
    const int d = idx & 255;
    const int s = (idx >> 8) & (SEG_ - 1);
    const int b = (idx >> 11) & 15;
    const int e = idx >> 15;

    const float nu = expf(pl[0 * 1024 + e * 256 + d]);
    const float th = expf(pl[1 * 1024 + e * 256 + d]);
    const float mag = expf(-nu);
    float sn, cs;
    sincosf(th, &sn, &cs);       // th <= 2*pi
    const float fr = mag * cs;
    const float fi = mag * sn;

    // f^SEGL via 7 complex squarings (SEGL = 128 = 2^7)
    float fLr = fr, fLi = fi;
#pragma unroll
    for (int q = 0; q < 7; q++) {
        const float r2 = fLr * fLr - fLi * fLi;
        const float i2 = 2.0f * fLr * fLi;
        fLr = r2; fLi = i2;
    }

    // incoming prefix: Horner over previous segment end-states
    float hr = 0.f, hi = 0.f;
    const size_t sbase = (((size_t)e * B_ + b) * SEG_) * D_ + d;
#pragma unroll 1
    for (int j = 0; j < s; j++) {
        const float er = g_segr[sbase + (size_t)j * D_];
        const float ei = g_segi[sbase + (size_t)j * D_];
        const float nr = fLr * hr - fLi * hi + er;
        const float ni = fLr * hi + fLi * hr + ei;
        hr = nr; hi = ni;
    }

    float* pr = g_u + (size_t)e * NDs + ((size_t)b * T_ + s * SEGL) * D_ + d;
    float* pi = pr + (size_t)4 * NDs;

#pragma unroll 1
    for (int t = 0; t < SEGL; t += 8) {
        float ur[8], ui[8];
#pragma unroll
        for (int j = 0; j < 8; j++) {
            ur[j] = pr[(size_t)j * D_];
            ui[j] = pi[(size_t)j * D_];
        }
#pragma unroll
        for (int j = 0; j < 8; j++) {
            const float nr = fr * hr - fi * hi + ur[j];
            const float ni = fr * hi + fi * hr + ui[j];
            hr = nr; hi = ni;
            pr[(size_t)j * D_] = hr;
            pi[(size_t)j * D_] = hi;
        }
        pr += 8 * D_;
        pi += 8 * D_;
    }

    if (s == SEG_ - 1) {
        // hidden: d_out[E*N*D + b*2048 + (0:hr | 1024:hi) + e*256 + d]
        float* hid = outp + (size_t)E_ * NDs;
        hid[(size_t)b * 2048 + e * 256 + d]        = hr;
        hid[(size_t)b * 2048 + 1024 + e * 256 + d] = hi;
    }
}

// ---------------------------------------------------------------------------
__device__ __forceinline__ float block_sum_256(float v, float* sh) {
#pragma unroll
    for (int o = 16; o > 0; o >>= 1) v += __shfl_down_sync(0xffffffffu, v, o);
    const int warp = threadIdx.x >> 5, lane = threadIdx.x & 31;
    __syncthreads();
    if (lane == 0) sh[warp] = v;
    __syncthreads();
    if (warp == 0) {
        v = (lane < 8) ? sh[lane] : 0.f;
#pragma unroll
        for (int o = 4; o > 0; o >>= 1) v += __shfl_down_sync(0xffffffffu, v, o);
        if (lane == 0) sh[0] = v;
    }
    __syncthreads();
    return sh[0];
}

// LayerNorm over (E, D) = 1024 elements per (b,t) row.
__global__ void ln_kernel(const float* __restrict__ ln_w,
                          const float* __restrict__ ln_b,
                          float* __restrict__ outp) {
    __shared__ float sh[32];
    const int n = blockIdx.x;        // b*T + t
    const int d = threadIdx.x;       // 0..255

    float v[E_];
    float s = 0.f;
#pragma unroll
    for (int e = 0; e < E_; e++) {
        v[e] = g_h2[(size_t)e * NDs + (size_t)n * 256 + d];
        s += v[e];
    }
    const float mean = block_sum_256(s, sh) * (1.0f / 1024.0f);

    float q = 0.f;
#pragma unroll
    for (int e = 0; e < E_; e++) {
        const float t = v[e] - mean;
        q += t * t;
    }
    const float var = block_sum_256(q, sh) * (1.0f / 1024.0f);
    const float rstd = rsqrtf(var + LN_EPS);

#pragma unroll
    for (int e = 0; e < E_; e++) {
        outp[(size_t)e * NDs + (size_t)n * 256 + d] =
            (v[e] - mean) * rstd * ln_w[e * 256 + d] + ln_b[e * 256 + d];
    }
}

// ---------------------------------------------------------------------------
extern "C" void kernel_launch(void* const* d_in, const int* in_sizes, int n_in,
                              void* d_out, int out_size) {
    const float* x          = (const float*)d_in[0];
    const float* in_proj_w  = (const float*)d_in[1];
    const float* in_proj_b  = (const float*)d_in[2];
    const float* params_log = (const float*)d_in[3];
    const float* mid_w      = (const float*)d_in[4];
    const float* mid_b      = (const float*)d_in[5];
    const float* ff_w1      = (const float*)d_in[6];
    const float* ff_b1      = (const float*)d_in[7];
    const float* ff_w2      = (const float*)d_in[8];
    const float* ff_b2      = (const float*)d_in[9];
    const float* ln_w       = (const float*)d_in[10];
    const float* ln_b       = (const float*)d_in[11];
    float* out = (float*)d_out;

    // opt-in to >48KB dynamic smem. Called unconditionally every invocation:
    // idempotent + deterministic (no static guards per harness rules), and a
    // pure host-side attribute set — not a stream op, so capture-safe.
    cudaFuncSetAttribute(tgemm_k<0>, cudaFuncAttributeMaxDynamicSharedMemorySize, SMEM_BYTES);
    cudaFuncSetAttribute(tgemm_k<1>, cudaFuncAttributeMaxDynamicSharedMemorySize, SMEM_BYTES);
    cudaFuncSetAttribute(tgemm_k<2>, cudaFuncAttributeMaxDynamicSharedMemorySize, SMEM_BYTES);
    cudaFuncSetAttribute(tgemm_k<3>, cudaFuncAttributeMaxDynamicSharedMemorySize, SMEM_BYTES);

    precompute_gamma<<<4, 256>>>(params_log);

    dim3 gin(NROW / 128, 2, 12);                 // 12 in_proj GEMMs
    tgemm_k<0><<<gin, 256, SMEM_BYTES>>>(x, in_proj_w, in_proj_b);

    const int scanThreads = E_ * B_ * SEG_ * D_;  // 131072
    scan_pass1<<<scanThreads / 256, 256>>>(params_log);
    scan_pass2<<<scanThreads / 256, 256>>>(params_log, out);

    dim3 ge(NROW / 128, 2, 4);
    tgemm_k<1><<<ge, 256, SMEM_BYTES>>>(mid_w, mid_b, nullptr);   // mid (dual-K) + o
    tgemm_k<2><<<ge, 256, SMEM_BYTES>>>(ff_w1, ff_b1, nullptr);   // gelu ffn1
    tgemm_k<3><<<ge, 256, SMEM_BYTES>>>(ff_w2, ff_b2, nullptr);   // ffn2 + residual

    ln_kernel<<<NROW, 256>>>(ln_w, ln_b, out);
}

// round 16
// speedup vs baseline: 3.6377x; 3.6377x over previous
#include <cuda_runtime.h>
#include <cuda_bf16.h>
#include <mma.h>
#include <math.h>

using namespace nvcuda;

// Problem constants
#define E_    4
#define D_    256
#define B_    16
#define T_    1024
#define NROW  (B_ * T_)          // 16384 rows (b*T + t)
#define LN_EPS 1e-5f

#define SEG_  8                  // scan segments
#define SEGL  (T_ / SEG_)        // 128 steps per segment (2^7)

#define ND_I  (NROW * D_)        // 4,194,304 elements per (k,e) activation tensor
static const size_t NDs = (size_t)NROW * D_;

// GEMM tile config (bf16 2-split, m16n16k16 wmma)
#define BM_ 128
#define BN_ 128
#define BK_ 16
#define ALDB_ 24    // A smem leading dim (bf16); 48B row stride, ldmatrix conflict-free
#define BLDB_ 136   // B smem leading dim (bf16); 272B row stride, conflict-free
#define CLD_ 20     // epilogue staging leading dim (floats)

// dynamic smem layout (bytes):
//   As: [2 buf][2 split][BM][ALDB] bf16 = 49152 B
//   Bs: [2 buf][2 split][BK][BLDB] bf16 = 34816 B
#define AS_BYTES (2 * 2 * BM_ * ALDB_ * 2)
#define BS_BYTES (2 * 2 * BK_ * BLDB_ * 2)
#define SMEM_BYTES (AS_BYTES + BS_BYTES)         // 83,968 B

// ---------------------------------------------------------------------------
// Scratch (device globals — no allocation allowed).
__device__ float g_u[3 * E_ * ND_I];          // 201 MB
__device__ float g_h1[E_ * ND_I];             // 67 MB
__device__ float g_h2[E_ * ND_I];             // 67 MB
__device__ float g_gamma[E_ * D_];            // 4 KB
__device__ float g_segr[E_ * B_ * SEG_ * D_]; // segment-end real
__device__ float g_segi[E_ * B_ * SEG_ * D_]; // segment-end imag

// ---------------------------------------------------------------------------
__global__ void precompute_gamma(const float* __restrict__ pl) {
    int i = blockIdx.x * blockDim.x + threadIdx.x;
    if (i < E_ * D_) {
        g_gamma[i] = expf(pl[2 * E_ * D_ + i]);   // params_log (3,E,D), gamma = k2
    }
}

__device__ __forceinline__ float gelu_exact(float x) {
    return 0.5f * x * (1.0f + erff(x * 0.70710678118654752440f));
}

// ---------------------------------------------------------------------------
// 2x-bf16-split tensor-core GEMM (hh + hl + lh in fp32 accum), 128x128x16
// tiles, DOUBLE-BUFFERED, ldmatrix-backed fragments, fused epilogues.
// EPI = 0: in_proj  z = k*4+e (12)  C = (A@W + b) * (k<2 ? gamma[e] : 1) -> g_u[z]
// EPI = 1: mid      z = e (4)  DUAL-K: acc = outR@W0 - outI@W1
//                   C = acc + b0 - b1 + o   -> g_u[8+e] (in place over o)
// EPI = 2: ffn1     z = e      C = gelu(out@W1 + b1) -> g_h1[e]
// EPI = 3: ffn2     z = e      C = h1@W2 + b2 + out  -> g_h2[e]
template <int EPI>
__global__ __launch_bounds__(256, 2) void tgemm_k(
    const float* __restrict__ P0,
    const float* __restrict__ P1,
    const float* __restrict__ P2)
{
    constexpr int BM = BM_, BN = BN_, BK = BK_;
    constexpr bool DUAL = (EPI == 1);
    constexpr int ALDB = ALDB_, BLDB = BLDB_, CLD = CLD_;

    extern __shared__ char smem[];
    typedef __nv_bfloat16 AsT[2][BM][ALDB];
    typedef __nv_bfloat16 BsT[2][BK][BLDB];
    AsT* As = (AsT*)smem;                        // 2 bufs
    BsT* Bs = (BsT*)(smem + AS_BYTES);           // 2 bufs
    // epilogue staging aliases the As region (dead after mainloop's final barrier)
    typedef float CstT[16][CLD];
    CstT* Cst = (CstT*)smem;                     // 8 warps x 16 x CLD

    const int tid = threadIdx.x;
    const int z = blockIdx.z;
    const int rowBase = blockIdx.x * BM;
    const int colBase = blockIdx.y * BN;

    const float *Aptr0, *Bptr0;
    const float *Aptr1 = nullptr, *Bptr1 = nullptr;

    if constexpr (EPI == 0) {
        Aptr0 = P0;                               // x
        Bptr0 = P1 + (size_t)z * 65536;           // in_proj_w[k][e]
    } else if constexpr (EPI == 1) {
        Aptr0 = g_u + (size_t)z * NDs;            // scan real output
        Bptr0 = P0 + (size_t)z * 65536;           // mid_w[0][e]
        Aptr1 = g_u + (size_t)(4 + z) * NDs;      // scan imag output
        Bptr1 = P0 + (size_t)(4 + z) * 65536;     // mid_w[1][e] (negated)
    } else if constexpr (EPI == 2) {
        Aptr0 = g_u + (size_t)(8 + z) * NDs;      // out
        Bptr0 = P0 + (size_t)z * 65536;           // ff_w1[e]
    } else {
        Aptr0 = g_h1 + (size_t)z * NDs;           // h1
        Bptr0 = P0 + (size_t)z * 65536;           // ff_w2[e]
    }

    // global-load assignments (2 float4 for A, 2 float4 for B per thread)
    const int arow = tid >> 2;            // 0..63 (and +64)
    const int akv  = (tid & 3) << 2;      // k sub-offset {0,4,8,12}
    const int brow = tid >> 5;            // 0..7 (and +8)
    const int bcol = (tid & 31) << 2;     // 0..124

    const int nsteps = DUAL ? 32 : 16;

    float4 ra0, ra1, rb0, rb1;

    auto ldg_step = [&](int step) {
        const float* Ag; const float* Bg; int k0; bool neg = false;
        if (!DUAL || step < 16) { Ag = Aptr0; Bg = Bptr0; k0 = step * BK; }
        else { Ag = Aptr1; Bg = Bptr1; k0 = (step - 16) * BK; neg = true; }
        ra0 = *(const float4*)&Ag[(size_t)(rowBase + arow)      * 256 + k0 + akv];
        ra1 = *(const float4*)&Ag[(size_t)(rowBase + arow + 64) * 256 + k0 + akv];
        rb0 = *(const float4*)&Bg[(size_t)(k0 + brow)     * 256 + colBase + bcol];
        rb1 = *(const float4*)&Bg[(size_t)(k0 + brow + 8) * 256 + colBase + bcol];
        if (DUAL && neg) {
            rb0.x = -rb0.x; rb0.y = -rb0.y; rb0.z = -rb0.z; rb0.w = -rb0.w;
            rb1.x = -rb1.x; rb1.y = -rb1.y; rb1.z = -rb1.z; rb1.w = -rb1.w;
        }
    };

    // split v into hi (bf16) + lo (bf16 of residual); pack pairs for 4B stores
    auto pack_split4 = [](const float* v, __nv_bfloat162* hi2, __nv_bfloat162* lo2) {
#pragma unroll
        for (int p = 0; p < 2; p++) {
            const float a = v[p * 2 + 0], b = v[p * 2 + 1];
            const __nv_bfloat16 ha = __float2bfloat16(a);
            const __nv_bfloat16 hb = __float2bfloat16(b);
            const __nv_bfloat16 la = __float2bfloat16(a - __bfloat162float(ha));
            const __nv_bfloat16 lb = __float2bfloat16(b - __bfloat162float(hb));
            hi2[p] = __nv_bfloat162(ha, hb);
            lo2[p] = __nv_bfloat162(la, lb);
        }
    };

    auto sts_step = [&](int buf) {
        __nv_bfloat162 h2[2], l2[2];
        pack_split4(&ra0.x, h2, l2);
        *(__nv_bfloat162*)&As[buf][0][arow][akv]     = h2[0];
        *(__nv_bfloat162*)&As[buf][0][arow][akv + 2] = h2[1];
        *(__nv_bfloat162*)&As[buf][1][arow][akv]     = l2[0];
        *(__nv_bfloat162*)&As[buf][1][arow][akv + 2] = l2[1];
        pack_split4(&ra1.x, h2, l2);
        *(__nv_bfloat162*)&As[buf][0][arow + 64][akv]     = h2[0];
        *(__nv_bfloat162*)&As[buf][0][arow + 64][akv + 2] = h2[1];
        *(__nv_bfloat162*)&As[buf][1][arow + 64][akv]     = l2[0];
        *(__nv_bfloat162*)&As[buf][1][arow + 64][akv + 2] = l2[1];
        pack_split4(&rb0.x, h2, l2);
        *(__nv_bfloat162*)&Bs[buf][0][brow][bcol]     = h2[0];
        *(__nv_bfloat162*)&Bs[buf][0][brow][bcol + 2] = h2[1];
        *(__nv_bfloat162*)&Bs[buf][1][brow][bcol]     = l2[0];
        *(__nv_bfloat162*)&Bs[buf][1][brow][bcol + 2] = l2[1];
        pack_split4(&rb1.x, h2, l2);
        *(__nv_bfloat162*)&Bs[buf][0][brow + 8][bcol]     = h2[0];
        *(__nv_bfloat162*)&Bs[buf][0][brow + 8][bcol + 2] = h2[1];
        *(__nv_bfloat162*)&Bs[buf][1][brow + 8][bcol]     = l2[0];
        *(__nv_bfloat162*)&Bs[buf][1][brow + 8][bcol + 2] = l2[1];
    };

    // warp tiling: 8 warps, warp tile 32x64 -> 2x4 wmma tiles of 16x16
    const int w    = tid >> 5;
    const int lane = tid & 31;
    const int wm   = w >> 1;     // 0..3, rows [wm*32, +32)
    const int wn   = w & 1;      // 0..1, cols [wn*64, +64)

    wmma::fragment<wmma::accumulator, 16, 16, 16, float> acc[2][4];
#pragma unroll
    for (int mi = 0; mi < 2; mi++)
#pragma unroll
        for (int ni = 0; ni < 4; ni++) wmma::fill_fragment(acc[mi][ni], 0.0f);

    // prologue: fill buffer 0
    ldg_step(0);
    sts_step(0);
    __syncthreads();

    int buf = 0;
#pragma unroll 1
    for (int step = 0; step < nsteps; ++step) {
        const bool has_next = (step + 1 < nsteps);
        if (has_next) ldg_step(step + 1);   // LDG latency hides under MMA phase

        wmma::fragment<wmma::matrix_a, 16, 16, 16, __nv_bfloat16,
                       wmma::row_major> ah[2], al[2];
#pragma unroll
        for (int mi = 0; mi < 2; mi++) {
            wmma::load_matrix_sync(ah[mi], &As[buf][0][wm * 32 + mi * 16][0], ALDB);
            wmma::load_matrix_sync(al[mi], &As[buf][1][wm * 32 + mi * 16][0], ALDB);
        }
#pragma unroll
        for (int ni = 0; ni < 4; ni++) {
            wmma::fragment<wmma::matrix_b, 16, 16, 16, __nv_bfloat16,
                           wmma::row_major> bh, bl;
            wmma::load_matrix_sync(bh, &Bs[buf][0][0][wn * 64 + ni * 16], BLDB);
            wmma::load_matrix_sync(bl, &Bs[buf][1][0][wn * 64 + ni * 16], BLDB);
#pragma unroll
            for (int mi = 0; mi < 2; mi++) {
                wmma::mma_sync(acc[mi][ni], ah[mi], bh, acc[mi][ni]);  // hi*hi
                wmma::mma_sync(acc[mi][ni], ah[mi], bl, acc[mi][ni]);  // hi*lo
                wmma::mma_sync(acc[mi][ni], al[mi], bh, acc[mi][ni]);  // lo*hi
            }
        }

        if (has_next) sts_step(buf ^ 1);    // fill idle buffer (consumed last iter)
        __syncthreads();                     // one barrier per iteration
        buf ^= 1;
    }

    // ---------------- epilogue (per-warp smem staging, aliases As) ----------
#pragma unroll
    for (int mi = 0; mi < 2; mi++) {
#pragma unroll
        for (int ni = 0; ni < 4; ni++) {
            wmma::store_matrix_sync(&Cst[w][0][0], acc[mi][ni], CLD, wmma::mem_row_major);
            __syncwarp();
#pragma unroll
            for (int q = lane; q < 256; q += 32) {
                const int r = q >> 4, c = q & 15;
                float v = Cst[w][r][c];
                const int n   = rowBase + wm * 32 + mi * 16 + r;
                const int col = colBase + wn * 64 + ni * 16 + c;
                const size_t idx = (size_t)n * 256 + col;

                if constexpr (EPI == 0) {
                    const int e = z & 3, k = z >> 2;
                    v += P2[(size_t)z * 256 + col];
                    if (k < 2) v *= g_gamma[e * 256 + col];
                    g_u[(size_t)z * NDs + idx] = v;
                } else if constexpr (EPI == 1) {
                    float* res = g_u + (size_t)(8 + z) * NDs;
                    v += P1[(size_t)z * 256 + col] - P1[(size_t)(4 + z) * 256 + col]
                         + res[idx];
                    res[idx] = v;   // "out" overwrites o in place
                } else if constexpr (EPI == 2) {
                    v = gelu_exact(v + P1[(size_t)z * 256 + col]);
                    g_h1[(size_t)z * NDs + idx] = v;
                } else {
                    const float* res = g_u + (size_t)(8 + z) * NDs;
                    v += P1[(size_t)z * 256 + col] + res[idx];
                    g_h2[(size_t)z * NDs + idx] = v;
                }
            }
            __syncwarp();
        }
    }
}

// ---------------------------------------------------------------------------
// Segmented LRU scan. f per (e,d): f = exp(-nu) * e^{i*theta}.
__global__ void scan_pass1(const float* __restrict__ pl) {
    const int idx = blockIdx.x * blockDim.x + threadIdx.x;  // (e,b,s,d)
    const int d = idx & 255;
    const int s = (idx >> 8) & (SEG_ - 1);
    const int b = (idx >> 11) & 15;
    const int e = idx >> 15;

    if (s == SEG_ - 1) return;   // last segment's end state is unused

    const float nu = expf(pl[0 * 1024 + e * 256 + d]);
    const float th = expf(pl[1 * 1024 + e * 256 + d]);
    const float mag = expf(-nu);
    float sn, cs;
    sincosf(th, &sn, &cs);       // th <= 2*pi: safe under fast math too
    const float fr = mag * cs;
    const float fi = mag * sn;

    const float* pr = g_u + (size_t)e * NDs + ((size_t)b * T_ + s * SEGL) * D_ + d;
    const float* pi = pr + (size_t)4 * NDs;

    float hr = 0.f, hi = 0.f;
#pragma unroll 1
    for (int t = 0; t < SEGL; t += 8) {
        float ur[8], ui[8];
#pragma unroll
        for (int j = 0; j < 8; j++) {
            ur[j] = pr[(size_t)j * D_];
            ui[j] = pi[(size_t)j * D_];
        }
#pragma unroll
        for (int j = 0; j < 8; j++) {
            const float nr = fr * hr - fi * hi + ur[j];
            const float ni = fr * hi + fi * hr + ui[j];
            hr = nr; hi = ni;
        }
        pr += 8 * D_;
        pi += 8 * D_;
    }

    const size_t si = (((size_t)e * B_ + b) * SEG_ + s) * D_ + d;
    g_segr[si] = hr;
    g_segi[si] = hi;
}

__global__ void scan_pass2(const float* __restrict__ pl, float* __restrict__ outp) {
    const int idx = blockIdx.x * blockDim.x + threadIdx.x;  // (e,b,s,d)
    const int d = idx & 255;
    const int s = (idx >> 8) & (SEG_ - 1);
    const int b = (idx >> 11) & 15;
    const int e = idx >> 15;

    const float nu = expf(pl[0 * 1024 + e * 256 + d]);
    const float th = expf(pl[1 * 1024 + e * 256 + d]);
    const float mag = expf(-nu);
    float sn, cs;
    sincosf(th, &sn, &cs);       // th <= 2*pi
    const float fr = mag * cs;
    const float fi = mag * sn;

    // f^SEGL via 7 complex squarings (SEGL = 128 = 2^7)
    float fLr = fr, fLi = fi;
#pragma unroll
    for (int q = 0; q < 7; q++) {
        const float r2 = fLr * fLr - fLi * fLi;
        const float i2 = 2.0f * fLr * fLi;
        fLr = r2; fLi = i2;
    }

    // incoming prefix: Horner over previous segment end-states
    float hr = 0.f, hi = 0.f;
    const size_t sbase = (((size_t)e * B_ + b) * SEG_) * D_ + d;
#pragma unroll 1
    for (int j = 0; j < s; j++) {
        const float er = g_segr[sbase + (size_t)j * D_];
        const float ei = g_segi[sbase + (size_t)j * D_];
        const float nr = fLr * hr - fLi * hi + er;
        const float ni = fLr * hi + fLi * hr + ei;
        hr = nr; hi = ni;
    }

    float* pr = g_u + (size_t)e * NDs + ((size_t)b * T_ + s * SEGL) * D_ + d;
    float* pi = pr + (size_t)4 * NDs;

#pragma unroll 1
    for (int t = 0; t < SEGL; t += 8) {
        float ur[8], ui[8];
#pragma unroll
        for (int j = 0; j < 8; j++) {
            ur[j] = pr[(size_t)j * D_];
            ui[j] = pi[(size_t)j * D_];
        }
#pragma unroll
        for (int j = 0; j < 8; j++) {
            const float nr = fr * hr - fi * hi + ur[j];
            const float ni = fr * hi + fi * hr + ui[j];
            hr = nr; hi = ni;
            pr[(size_t)j * D_] = hr;
            pi[(size_t)j * D_] = hi;
        }
        pr += 8 * D_;
        pi += 8 * D_;
    }

    if (s == SEG_ - 1) {
        float* hid = outp + (size_t)E_ * NDs;
        hid[(size_t)b * 2048 + e * 256 + d]        = hr;
        hid[(size_t)b * 2048 + 1024 + e * 256 + d] = hi;
    }
}

// ---------------------------------------------------------------------------
__device__ __forceinline__ float block_sum_256(float v, float* sh) {
#pragma unroll
    for (int o = 16; o > 0; o >>= 1) v += __shfl_down_sync(0xffffffffu, v, o);
    const int warp = threadIdx.x >> 5, lane = threadIdx.x & 31;
    __syncthreads();
    if (lane == 0) sh[warp] = v;
    __syncthreads();
    if (warp == 0) {
        v = (lane < 8) ? sh[lane] : 0.f;
#pragma unroll
        for (int o = 4; o > 0; o >>= 1) v += __shfl_down_sync(0xffffffffu, v, o);
        if (lane == 0) sh[0] = v;
    }
    __syncthreads();
    return sh[0];
}

// LayerNorm over (E, D) = 1024 elements per (b,t) row.
__global__ void ln_kernel(const float* __restrict__ ln_w,
                          const float* __restrict__ ln_b,
                          float* __restrict__ outp) {
    __shared__ float sh[32];
    const int n = blockIdx.x;        // b*T + t
    const int d = threadIdx.x;       // 0..255

    float v[E_];
    float s = 0.f;
#pragma unroll
    for (int e = 0; e < E_; e++) {
        v[e] = g_h2[(size_t)e * NDs + (size_t)n * 256 + d];
        s += v[e];
    }
    const float mean = block_sum_256(s, sh) * (1.0f / 1024.0f);

    float q = 0.f;
#pragma unroll
    for (int e = 0; e < E_; e++) {
        const float t = v[e] - mean;
        q += t * t;
    }
    const float var = block_sum_256(q, sh) * (1.0f / 1024.0f);
    const float rstd = rsqrtf(var + LN_EPS);

#pragma unroll
    for (int e = 0; e < E_; e++) {
        outp[(size_t)e * NDs + (size_t)n * 256 + d] =
            (v[e] - mean) * rstd * ln_w[e * 256 + d] + ln_b[e * 256 + d];
    }
}

// ---------------------------------------------------------------------------
extern "C" void kernel_launch(void* const* d_in, const int* in_sizes, int n_in,
                              void* d_out, int out_size) {
    const float* x          = (const float*)d_in[0];
    const float* in_proj_w  = (const float*)d_in[1];
    const float* in_proj_b  = (const float*)d_in[2];
    const float* params_log = (const float*)d_in[3];
    const float* mid_w      = (const float*)d_in[4];
    const float* mid_b      = (const float*)d_in[5];
    const float* ff_w1      = (const float*)d_in[6];
    const float* ff_b1      = (const float*)d_in[7];
    const float* ff_w2      = (const float*)d_in[8];
    const float* ff_b2      = (const float*)d_in[9];
    const float* ln_w       = (const float*)d_in[10];
    const float* ln_b       = (const float*)d_in[11];
    float* out = (float*)d_out;

    // opt-in to >48KB dynamic smem (idempotent, host-side, capture-safe)
    cudaFuncSetAttribute(tgemm_k<0>, cudaFuncAttributeMaxDynamicSharedMemorySize, SMEM_BYTES);
    cudaFuncSetAttribute(tgemm_k<1>, cudaFuncAttributeMaxDynamicSharedMemorySize, SMEM_BYTES);
    cudaFuncSetAttribute(tgemm_k<2>, cudaFuncAttributeMaxDynamicSharedMemorySize, SMEM_BYTES);
    cudaFuncSetAttribute(tgemm_k<3>, cudaFuncAttributeMaxDynamicSharedMemorySize, SMEM_BYTES);

    precompute_gamma<<<4, 256>>>(params_log);

    dim3 gin(NROW / 128, 2, 12);                 // 12 in_proj GEMMs
    tgemm_k<0><<<gin, 256, SMEM_BYTES>>>(x, in_proj_w, in_proj_b);

    const int scanThreads = E_ * B_ * SEG_ * D_;  // 131072
    scan_pass1<<<scanThreads / 256, 256>>>(params_log);
    scan_pass2<<<scanThreads / 256, 256>>>(params_log, out);

    dim3 ge(NROW / 128, 2, 4);
    tgemm_k<1><<<ge, 256, SMEM_BYTES>>>(mid_w, mid_b, nullptr);   // mid (dual-K) + o
    tgemm_k<2><<<ge, 256, SMEM_BYTES>>>(ff_w1, ff_b1, nullptr);   // gelu ffn1
    tgemm_k<3><<<ge, 256, SMEM_BYTES>>>(ff_w2, ff_b2, nullptr);   // ffn2 + residual

    ln_kernel<<<NROW, 256>>>(ln_w, ln_b, out);
}